// round 5
// baseline (speedup 1.0000x reference)
#include <cuda_runtime.h>
#include <cuda_bf16.h>

// WeightedNHotEncodingLayer: out[row, ids[k]] += w[k] for k in row's CSR range.
// Output (16384 x 8192 fp32 = 512MB) dominates: write it exactly once.
//
// R2 insight: full smem-row zero + readback saturated the LSU (L1=63.4%) and
// throttled the STG stream (DRAM stuck at 71.8%). Only ~50/8192 buckets are
// touched per row -> track them with a 1KB bitmap; untouched float4 slots are
// stored as a register-constant zero with NO shared-memory traffic.
// Phase 3 is word-major: one bitmap LDS covers 8 consecutive float4 stores.

#define MAX_ROWS 32768
__device__ int g_row_offsets[MAX_ROWS];

__global__ void __launch_bounds__(1024)
scan_row_lengths(const int* __restrict__ lens,
                 int* __restrict__ offs, int n) {
    __shared__ int partial[1024];
    const int t = threadIdx.x;
    const int items = (n + 1023) >> 10;
    const int base = t * items;

    int s = 0;
    if ((items & 3) == 0 && base + items <= n) {
        const int4* l4 = reinterpret_cast<const int4*>(lens + base);
        #pragma unroll 4
        for (int j = 0; j < items / 4; j++) {
            int4 v = __ldg(&l4[j]);
            s += v.x + v.y + v.z + v.w;
        }
    } else {
        for (int j = 0; j < items; j++) {
            int i = base + j;
            if (i < n) s += lens[i];
        }
    }
    partial[t] = s;
    __syncthreads();
    #pragma unroll
    for (int d = 1; d < 1024; d <<= 1) {
        int v = (t >= d) ? partial[t - d] : 0;
        __syncthreads();
        partial[t] += v;
        __syncthreads();
    }
    int run = partial[t] - s;
    for (int j = 0; j < items; j++) {
        int i = base + j;
        if (i < n) {
            offs[i] = run;
            run += lens[i];
        }
    }
}

__global__ void __launch_bounds__(256)
nhot_row_kernel(const int* __restrict__ ids,
                const float* __restrict__ w,
                const int* __restrict__ lens,
                const int* __restrict__ offs,
                float* __restrict__ out,
                int nb) {
    // dyn smem: [ srow: nb floats ][ bitmap: nb/32 uints ]
    extern __shared__ float srow[];
    unsigned* bitmap = reinterpret_cast<unsigned*>(srow + nb);

    const int row = blockIdx.x;
    const int t   = threadIdx.x;
    const int nbw = nb >> 5;   // bitmap words (256): 1 word = 32 buckets = 8 float4 slots

    const int len   = lens[row];
    const int start = offs[row];

    // Phase 1: zero bitmap; zero only the touched srow entries.
    for (int i = t; i < nbw; i += 256) bitmap[i] = 0u;
    for (int j = t; j < len; j += 256) {
        int id = __ldg(&ids[start + j]);
        srow[id] = 0.f;                    // duplicate plain stores of 0: benign
    }
    __syncthreads();

    // Phase 2: accumulate (handles duplicate ids) and mark bitmap.
    for (int j = t; j < len; j += 256) {
        int id  = __ldg(&ids[start + j]);
        float v = __ldg(&w[start + j]);
        atomicAdd(&srow[id], v);
        atomicOr(&bitmap[id >> 5], 1u << (id & 31));
    }
    __syncthreads();

    // Phase 3 (word-major): each thread owns bitmap word wi, i.e. 32
    // consecutive buckets = 8 float4 stores. One bitmap LDS per 8 stores;
    // untouched slots emit a register-zero with no srow read.
    float4* o4 = reinterpret_cast<float4*>(out + (size_t)row * nb);
    for (int wi = t; wi < nbw; wi += 256) {
        unsigned wbits = bitmap[wi];
        const int slot0 = wi << 3;          // first float4 slot of this word
        #pragma unroll
        for (int k = 0; k < 8; k++) {
            unsigned nib = (wbits >> (k << 2)) & 0xFu;
            float4 v = make_float4(0.f, 0.f, 0.f, 0.f);
            if (nib) {
                int b = (slot0 + k) << 2;   // bucket index
                if (nib & 1u) v.x = srow[b + 0];
                if (nib & 2u) v.y = srow[b + 1];
                if (nib & 4u) v.z = srow[b + 2];
                if (nib & 8u) v.w = srow[b + 3];
            }
            __stcs(&o4[slot0 + k], v);
        }
    }
}

extern "C" void kernel_launch(void* const* d_in, const int* in_sizes, int n_in,
                              void* d_out, int out_size) {
    const int*   ids  = (const int*)d_in[0];     // values (NNZ,1) int32
    const int*   lens = (const int*)d_in[1];     // row_lengths (B,1) int32
    const float* w    = (const float*)d_in[2];   // weight_values (NNZ,1) f32
    // d_in[3] = weight_row_lengths (identical; unused)
    float* out = (float*)d_out;

    const int B  = in_sizes[1];            // 16384 rows
    const int nb = out_size / B;           // 8192 buckets

    int* offs;
    cudaGetSymbolAddress((void**)&offs, g_row_offsets);

    scan_row_lengths<<<1, 1024>>>(lens, offs, B);

    const size_t smem = (size_t)nb * sizeof(float) + (size_t)(nb >> 5) * sizeof(unsigned);
    nhot_row_kernel<<<B, 256, smem>>>(ids, w, lens, offs, out, nb);
}

// round 11
// speedup vs baseline: 2.4426x; 2.4426x over previous
#include <cuda_runtime.h>
#include <cuda_bf16.h>

// WeightedNHotEncodingLayer: out[row, ids[k]] += w[k] for k in row's CSR range.
// Output (16384 x 8192 fp32 = 512MB) dominates: write it exactly once.
//
// R2 lesson: full smem-row zero+readback saturated the LSU (L1=63%) and capped
// DRAM at 72%. R5 lesson: "word-major" stores (8 consecutive float4 per thread)
// destroyed coalescing (32 lines per STG issue) -> DRAM 30%. This version:
// bitmap of touched buckets (cheap smem) + SLOT-MAJOR coalesced stores
// (lane-consecutive float4, one scalar broadcast bitmap LDS per slot).

#define MAX_ROWS 32768
__device__ int g_row_offsets[MAX_ROWS];

__global__ void __launch_bounds__(1024)
scan_row_lengths(const int* __restrict__ lens,
                 int* __restrict__ offs, int n) {
    __shared__ int partial[1024];
    const int t = threadIdx.x;
    const int items = (n + 1023) >> 10;
    const int base = t * items;

    int s = 0;
    if ((items & 3) == 0 && base + items <= n) {
        const int4* l4 = reinterpret_cast<const int4*>(lens + base);
        #pragma unroll 4
        for (int j = 0; j < items / 4; j++) {
            int4 v = __ldg(&l4[j]);
            s += v.x + v.y + v.z + v.w;
        }
    } else {
        for (int j = 0; j < items; j++) {
            int i = base + j;
            if (i < n) s += lens[i];
        }
    }
    partial[t] = s;
    __syncthreads();
    #pragma unroll
    for (int d = 1; d < 1024; d <<= 1) {
        int v = (t >= d) ? partial[t - d] : 0;
        __syncthreads();
        partial[t] += v;
        __syncthreads();
    }
    int run = partial[t] - s;
    for (int j = 0; j < items; j++) {
        int i = base + j;
        if (i < n) {
            offs[i] = run;
            run += lens[i];
        }
    }
}

__global__ void __launch_bounds__(256)
nhot_row_kernel(const int* __restrict__ ids,
                const float* __restrict__ w,
                const int* __restrict__ lens,
                const int* __restrict__ offs,
                float* __restrict__ out,
                int nb) {
    // dyn smem: [ srow: nb floats ][ bitmap: nb/32 uints ]
    extern __shared__ float srow[];
    unsigned* bitmap = reinterpret_cast<unsigned*>(srow + nb);

    const int row = blockIdx.x;
    const int t   = threadIdx.x;
    const int nb4 = nb >> 2;   // float4 slots (2048)
    const int nbw = nb >> 5;   // bitmap words (256)

    const int len   = lens[row];
    const int start = offs[row];

    // Phase 1: zero bitmap; zero only the touched srow entries.
    for (int i = t; i < nbw; i += 256) bitmap[i] = 0u;
    for (int j = t; j < len; j += 256) {
        int id = __ldg(&ids[start + j]);
        srow[id] = 0.f;                    // duplicate plain stores of 0: benign
    }
    __syncthreads();

    // Phase 2: accumulate (handles duplicate ids) and mark bitmap.
    for (int j = t; j < len; j += 256) {
        int id  = __ldg(&ids[start + j]);
        float v = __ldg(&w[start + j]);
        atomicAdd(&srow[id], v);
        atomicOr(&bitmap[id >> 5], 1u << (id & 31));
    }
    __syncthreads();

    // Phase 3 (slot-major, coalesced): thread t stores slots t, t+256, ...
    // Lane-consecutive float4 -> 4 lines per warp store. One scalar bitmap
    // LDS per slot (8 adjacent lanes share a word -> broadcast). Untouched
    // slots emit a register zero with no srow read.
    float4* o4 = reinterpret_cast<float4*>(out + (size_t)row * nb);
    #pragma unroll 8
    for (int i = t; i < nb4; i += 256) {
        unsigned wbits = bitmap[i >> 3];                 // word covers 8 slots
        unsigned nib   = (wbits >> ((i & 7) << 2)) & 0xFu;
        float4 v = make_float4(0.f, 0.f, 0.f, 0.f);
        if (nib) {
            int b = i << 2;
            if (nib & 1u) v.x = srow[b + 0];
            if (nib & 2u) v.y = srow[b + 1];
            if (nib & 4u) v.z = srow[b + 2];
            if (nib & 8u) v.w = srow[b + 3];
        }
        __stcs(&o4[i], v);
    }
}

extern "C" void kernel_launch(void* const* d_in, const int* in_sizes, int n_in,
                              void* d_out, int out_size) {
    const int*   ids  = (const int*)d_in[0];     // values (NNZ,1) int32
    const int*   lens = (const int*)d_in[1];     // row_lengths (B,1) int32
    const float* w    = (const float*)d_in[2];   // weight_values (NNZ,1) f32
    // d_in[3] = weight_row_lengths (identical; unused)
    float* out = (float*)d_out;

    const int B  = in_sizes[1];            // 16384 rows
    const int nb = out_size / B;           // 8192 buckets

    int* offs;
    cudaGetSymbolAddress((void**)&offs, g_row_offsets);

    scan_row_lengths<<<1, 1024>>>(lens, offs, B);

    const size_t smem = (size_t)nb * sizeof(float) + (size_t)(nb >> 5) * sizeof(unsigned);
    nhot_row_kernel<<<B, 256, smem>>>(ids, w, lens, offs, out, nb);
}